// round 6
// baseline (speedup 1.0000x reference)
#include <cuda_runtime.h>
#include <math.h>

// Problem shape (fixed by the dataset: B=32, T=1024, D=1024, M=1024)
namespace {
constexpr int Mm = 1024;             // number of memories (K in sinkhorn)
constexpr int Dd = 1024;             // feature dim
constexpr int Nn = 32768;            // tokens = B*T
}

// Scratch (device globals: allocation-free, per harness rules)
__device__ float  g_E[(size_t)Mm * (size_t)Nn];   // exp(sim/tau), 128 MiB
__device__ float  g_Xn[(size_t)Nn * (size_t)Dd];  // l2-normalized tokens (fp32), 128 MiB
__device__ float  g_Mn[(size_t)Mm * (size_t)Dd];  // l2-normalized memories (fp32), 4 MiB
__device__ double g_R64[Mm];                      // sinkhorn row factors (fp64)
__device__ float  g_Rf[Mm];                       // fp32 copy for argmax scan
__device__ float  g_C[Nn];                        // sinkhorn col factors
__device__ int    g_idx[Nn];                      // argmax memory index per token

// ---------------------------------------------------------------------------
// block-wide fp64 sum over 256 threads; result valid in thread 0
__device__ __forceinline__ double block_reduce_f64_256(double s) {
    #pragma unroll
    for (int o = 16; o; o >>= 1) s += __shfl_down_sync(0xffffffffu, s, o);
    __shared__ double red[8];
    if ((threadIdx.x & 31) == 0) red[threadIdx.x >> 5] = s;
    __syncthreads();
    if (threadIdx.x < 32) {
        s = (threadIdx.x < 8) ? red[threadIdx.x] : 0.0;
        #pragma unroll
        for (int o = 4; o; o >>= 1) s += __shfl_down_sync(0xffffffffu, s, o);
    }
    return s;
}

// ---------------------------------------------------------------------------
// Elementwise l2-normalize each row, mimicking the reference's fp32 rounding:
//   r = 1.0f / sqrtf(max((float)sumsq, 1e-12f));  out[d] = in[d] * r  (fp32)
// Destination is a __device__ global selected by template arg (NEVER pass a
// __device__ symbol as a host-side kernel argument — that was the R3 bug).
template <int TARGET>   // 0 -> g_Xn, 1 -> g_Mn
__global__ void an_normalize_kernel(const float* __restrict__ x) {
    const float4* src = reinterpret_cast<const float4*>(x + (size_t)blockIdx.x * Dd);
    const float4 v = src[threadIdx.x];
    double s = (double)v.x * v.x + (double)v.y * v.y + (double)v.z * v.z + (double)v.w * v.w;
    s = block_reduce_f64_256(s);
    __shared__ float rbc;
    if (threadIdx.x == 0) rbc = 1.0f / sqrtf(fmaxf((float)s, 1e-12f));
    __syncthreads();
    const float r = rbc;
    float4 o;
    o.x = v.x * r; o.y = v.y * r; o.z = v.z * r; o.w = v.w * r;
    float* dst = (TARGET == 0) ? g_Xn : g_Mn;
    reinterpret_cast<float4*>(dst + (size_t)blockIdx.x * Dd)[threadIdx.x] = o;
}

// ---------------------------------------------------------------------------
// GEMM on pre-normalized inputs: sim[m][n] = sum_d Mn[m][d] * Xn[n][d], fp32
// single-accumulator FMA in ascending d order (matches Eigen/cublas-SIMT
// sequential accumulation). Epilogue: E = expf(sim / 0.05f).
// 128x128 tile, BK=16, 256 threads, 8x8 register tile per thread.
__global__ __launch_bounds__(256, 2)
void an_gemm_exp_kernel() {
    constexpr int BM = 128, BN = 128, BK = 16, TM = 8, TN = 8;
    __shared__ __align__(16) float As[BK][BM + 4];
    __shared__ __align__(16) float Bs[BK][BN + 4];

    const float* __restrict__ A = g_Mn;
    const float* __restrict__ B = g_Xn;

    const int tid = threadIdx.x;
    const int tx  = tid & 15;
    const int ty  = tid >> 4;
    const int m0  = blockIdx.y * BM;
    const int n0  = blockIdx.x * BN;

    const int lr = tid >> 2;           // 0..63
    const int lc = (tid & 3) << 2;     // 0,4,8,12

    float acc[TM][TN] = {};

    for (int kt = 0; kt < Dd; kt += BK) {
        const float4 a0 = *reinterpret_cast<const float4*>(A + (size_t)(m0 + lr)      * Dd + kt + lc);
        const float4 a1 = *reinterpret_cast<const float4*>(A + (size_t)(m0 + lr + 64) * Dd + kt + lc);
        const float4 b0 = *reinterpret_cast<const float4*>(B + (size_t)(n0 + lr)      * Dd + kt + lc);
        const float4 b1 = *reinterpret_cast<const float4*>(B + (size_t)(n0 + lr + 64) * Dd + kt + lc);

        As[lc + 0][lr]      = a0.x; As[lc + 1][lr]      = a0.y;
        As[lc + 2][lr]      = a0.z; As[lc + 3][lr]      = a0.w;
        As[lc + 0][lr + 64] = a1.x; As[lc + 1][lr + 64] = a1.y;
        As[lc + 2][lr + 64] = a1.z; As[lc + 3][lr + 64] = a1.w;
        Bs[lc + 0][lr]      = b0.x; Bs[lc + 1][lr]      = b0.y;
        Bs[lc + 2][lr]      = b0.z; Bs[lc + 3][lr]      = b0.w;
        Bs[lc + 0][lr + 64] = b1.x; Bs[lc + 1][lr + 64] = b1.y;
        Bs[lc + 2][lr + 64] = b1.z; Bs[lc + 3][lr + 64] = b1.w;
        __syncthreads();

        #pragma unroll
        for (int k = 0; k < BK; k++) {
            float ra[TM], rb[TN];
            *reinterpret_cast<float4*>(&ra[0]) = *reinterpret_cast<const float4*>(&As[k][ty * TM]);
            *reinterpret_cast<float4*>(&ra[4]) = *reinterpret_cast<const float4*>(&As[k][ty * TM + 4]);
            *reinterpret_cast<float4*>(&rb[0]) = *reinterpret_cast<const float4*>(&Bs[k][tx * TN]);
            *reinterpret_cast<float4*>(&rb[4]) = *reinterpret_cast<const float4*>(&Bs[k][tx * TN + 4]);
            #pragma unroll
            for (int i = 0; i < TM; i++)
                #pragma unroll
                for (int j = 0; j < TN; j++)
                    acc[i][j] = fmaf(ra[i], rb[j], acc[i][j]);
        }
        __syncthreads();
    }

    // Epilogue: E = expf(sim / 0.05f)  (IEEE division, matching out/SINKHORN_TEMP)
    #pragma unroll
    for (int i = 0; i < TM; i++) {
        const int gm = m0 + ty * TM + i;
        float4 e0, e1;
        e0.x = expf(acc[i][0] / 0.05f);
        e0.y = expf(acc[i][1] / 0.05f);
        e0.z = expf(acc[i][2] / 0.05f);
        e0.w = expf(acc[i][3] / 0.05f);
        e1.x = expf(acc[i][4] / 0.05f);
        e1.y = expf(acc[i][5] / 0.05f);
        e1.z = expf(acc[i][6] / 0.05f);
        e1.w = expf(acc[i][7] / 0.05f);
        float* dst = g_E + (size_t)gm * Nn + n0 + tx * TN;
        *reinterpret_cast<float4*>(dst)     = e0;
        *reinterpret_cast<float4*>(dst + 4) = e1;
    }
}

// ---------------------------------------------------------------------------
// Row pass: R[m] = 1 / (K * sum_n E[m][n] * (USE_C ? C[n] : 1)), fp64 accumulate.
template <bool USE_C>
__global__ void an_row_reduce_kernel() {
    const int m = blockIdx.x;
    const float4* e  = reinterpret_cast<const float4*>(g_E + (size_t)m * Nn);
    const float4* c4 = reinterpret_cast<const float4*>(g_C);
    double s = 0.0;
    for (int i = threadIdx.x; i < Nn / 4; i += 256) {
        const float4 v = e[i];
        if (USE_C) {
            const float4 c = c4[i];
            s += (double)(v.x * c.x) + (double)(v.y * c.y)
               + (double)(v.z * c.z) + (double)(v.w * c.w);
        } else {
            s += (double)v.x + (double)v.y + (double)v.z + (double)v.w;
        }
    }
    s = block_reduce_f64_256(s);
    if (threadIdx.x == 0) {
        double r = 1.0 / ((double)Mm * s);
        g_R64[m] = r;
        g_Rf[m]  = (float)r;
    }
}

// Col pass: C[n] = 1 / (B * sum_m E[m][n] * R[m]); one thread per column, fp64 accum.
__global__ void an_col_reduce_kernel() {
    __shared__ float sR[Mm];
    for (int i = threadIdx.x; i < Mm; i += 256) sR[i] = g_Rf[i];
    __syncthreads();
    const int n = blockIdx.x * blockDim.x + threadIdx.x;
    double s = 0.0;
    #pragma unroll 8
    for (int m = 0; m < Mm; m++)
        s += (double)(g_E[(size_t)m * Nn + n] * sR[m]);
    g_C[n] = (float)(1.0 / ((double)Nn * s));
}

// Argmax pass: idx[n] = argmax_m E[m][n] * R3[m] (fp32, strict '>' keeps first
// max = jnp.argmax tie-breaking; col factors are m-independent and drop out).
__global__ void an_argmax_kernel() {
    __shared__ float sR[Mm];
    for (int i = threadIdx.x; i < Mm; i += 256) sR[i] = g_Rf[i];
    __syncthreads();
    const int n = blockIdx.x * blockDim.x + threadIdx.x;
    float best = -1.0f;
    int   bi   = 0;
    #pragma unroll 4
    for (int m = 0; m < Mm; m++) {
        const float v = g_E[(size_t)m * Nn + n] * sR[m];
        if (v > best) { best = v; bi = m; }
    }
    g_idx[n] = bi;
}

// Output: out[n][d] = 0.5 * (proj[n][d] + memory[idx[n]][d])
__global__ void an_output_kernel(const float* __restrict__ proj,
                                 const float* __restrict__ mem,
                                 float* __restrict__ out) {
    const int n  = blockIdx.x;
    const int id = g_idx[n];
    const float4 p = reinterpret_cast<const float4*>(proj + (size_t)n  * Dd)[threadIdx.x];
    const float4 q = reinterpret_cast<const float4*>(mem  + (size_t)id * Dd)[threadIdx.x];
    float4 o;
    o.x = 0.5f * (p.x + q.x);
    o.y = 0.5f * (p.y + q.y);
    o.z = 0.5f * (p.z + q.z);
    o.w = 0.5f * (p.w + q.w);
    reinterpret_cast<float4*>(out + (size_t)n * Dd)[threadIdx.x] = o;
}

// ---------------------------------------------------------------------------
extern "C" void kernel_launch(void* const* d_in, const int* in_sizes, int n_in,
                              void* d_out, int out_size) {
    const float* proj = (const float*)d_in[0];   // [32,1024,1024] -> [N, D]
    const float* mem  = (const float*)d_in[1];   // [1024,1024]    -> [M, D]
    if (n_in >= 2 && in_sizes[0] < in_sizes[1]) {
        const float* t = proj; proj = mem; mem = t;
    }
    float* out = (float*)d_out;

    // 1) l2-normalize rows (fp32 elementwise, like the reference)
    an_normalize_kernel<0><<<Nn, 256>>>(proj);
    an_normalize_kernel<1><<<Mm, 256>>>(mem);

    // 2) E = exp(sim / tau), sim from normalized vectors (ascending-k fp32 FMA)
    dim3 ggrid(Nn / 128, Mm / 128);
    an_gemm_exp_kernel<<<ggrid, 256>>>();

    // 3) Sinkhorn factors, fp64 accumulation (argmax over m only needs R3)
    an_row_reduce_kernel<false><<<Mm, 256>>>();      // R1
    an_col_reduce_kernel<<<Nn / 256, 256>>>();       // C1
    an_row_reduce_kernel<true><<<Mm, 256>>>();       // R2
    an_col_reduce_kernel<<<Nn / 256, 256>>>();       // C2
    an_row_reduce_kernel<true><<<Mm, 256>>>();       // R3

    // 4) per-token argmax over memories, then fused gather + mean
    an_argmax_kernel<<<Nn / 256, 256>>>();
    an_output_kernel<<<Nn, 256>>>(proj, mem, out);
}

// round 7
// speedup vs baseline: 1.2861x; 1.2861x over previous
#include <cuda_runtime.h>
#include <math.h>

// Problem shape (fixed by the dataset: B=32, T=1024, D=1024, M=1024)
namespace {
constexpr int Mm = 1024;             // number of memories (K in sinkhorn)
constexpr int Dd = 1024;             // feature dim
constexpr int Nn = 32768;            // tokens = B*T
}

// Scratch (device globals: allocation-free, per harness rules)
__device__ float  g_E[(size_t)Mm * (size_t)Nn];   // exp(sim/tau), 128 MiB
__device__ float  g_Xn[(size_t)Nn * (size_t)Dd];  // l2-normalized tokens (fp32), 128 MiB
__device__ float  g_Mn[(size_t)Mm * (size_t)Dd];  // l2-normalized memories (fp32), 4 MiB
__device__ double g_R64[Mm];                      // sinkhorn row factors (fp64)
__device__ float  g_Rf[Mm];                       // fp32 copy for argmax scan
__device__ float  g_C[Nn];                        // sinkhorn col factors
__device__ int    g_idx[Nn];                      // argmax memory index per token

// ---------------------------------------------------------------------------
// packed f32x2 helpers (FFMA2: 2 IEEE fp32 FMAs per issue slot; lanes bit-
// identical to scalar FFMA, so per-dot accumulation order is unchanged)
__device__ __forceinline__ void ffma2(unsigned long long& d,
                                      unsigned long long a,
                                      unsigned long long b) {
    asm("fma.rn.f32x2 %0, %1, %2, %0;" : "+l"(d) : "l"(a), "l"(b));
}
__device__ __forceinline__ unsigned long long dupf(float x) {
    unsigned long long r;
    unsigned int u = __float_as_uint(x);
    asm("mov.b64 %0, {%1, %1};" : "=l"(r) : "r"(u));
    return r;
}
__device__ __forceinline__ void unpack2(unsigned long long v, float& lo, float& hi) {
    unsigned int l, h;
    asm("mov.b64 {%0, %1}, %2;" : "=r"(l), "=r"(h) : "l"(v));
    lo = __uint_as_float(l);
    hi = __uint_as_float(h);
}

// ---------------------------------------------------------------------------
// block-wide fp64 sum over 256 threads; result valid in thread 0
__device__ __forceinline__ double block_reduce_f64_256(double s) {
    #pragma unroll
    for (int o = 16; o; o >>= 1) s += __shfl_down_sync(0xffffffffu, s, o);
    __shared__ double red[8];
    if ((threadIdx.x & 31) == 0) red[threadIdx.x >> 5] = s;
    __syncthreads();
    if (threadIdx.x < 32) {
        s = (threadIdx.x < 8) ? red[threadIdx.x] : 0.0;
        #pragma unroll
        for (int o = 4; o; o >>= 1) s += __shfl_down_sync(0xffffffffu, s, o);
    }
    return s;
}

// ---------------------------------------------------------------------------
// Elementwise l2-normalize each row:
//   r = 1.0f / sqrtf(max((float)sumsq, 1e-12f));  out[d] = in[d] * r  (fp32)
template <int TARGET>   // 0 -> g_Xn, 1 -> g_Mn
__global__ void an_normalize_kernel(const float* __restrict__ x) {
    const float4* src = reinterpret_cast<const float4*>(x + (size_t)blockIdx.x * Dd);
    const float4 v = src[threadIdx.x];
    // group-of-2 fp32 pre-sum, then fp64 (norm perturbation ~1e-10: negligible)
    double s = (double)(v.x * v.x + v.y * v.y) + (double)(v.z * v.z + v.w * v.w);
    s = block_reduce_f64_256(s);
    __shared__ float rbc;
    if (threadIdx.x == 0) rbc = 1.0f / sqrtf(fmaxf((float)s, 1e-12f));
    __syncthreads();
    const float r = rbc;
    float4 o;
    o.x = v.x * r; o.y = v.y * r; o.z = v.z * r; o.w = v.w * r;
    float* dst = (TARGET == 0) ? g_Xn : g_Mn;
    reinterpret_cast<float4*>(dst + (size_t)blockIdx.x * Dd)[threadIdx.x] = o;
}

// ---------------------------------------------------------------------------
// GEMM on pre-normalized inputs: sim[m][n] = sum_d Mn[m][d] * Xn[n][d].
// Accumulators packed pairwise along m (f32x2); each lane keeps the exact
// single-accumulator ascending-d fp32 FMA chain -> bit-identical to scalar.
// Epilogue: E = expf(sim / 0.05f).
__global__ __launch_bounds__(256, 2)
void an_gemm_exp_kernel() {
    constexpr int BM = 128, BN = 128, BK = 16, TM = 8, TN = 8;
    __shared__ __align__(16) float As[BK][BM + 4];
    __shared__ __align__(16) float Bs[BK][BN + 4];

    const float* __restrict__ A = g_Mn;
    const float* __restrict__ B = g_Xn;

    const int tid = threadIdx.x;
    const int tx  = tid & 15;
    const int ty  = tid >> 4;
    const int m0  = blockIdx.y * BM;
    const int n0  = blockIdx.x * BN;

    const int lr = tid >> 2;           // 0..63
    const int lc = (tid & 3) << 2;     // 0,4,8,12

    // acc2[ii][j]: lo = row ty*TM+2ii, hi = row ty*TM+2ii+1, col tx*TN+j
    unsigned long long acc2[TM / 2][TN] = {};

    for (int kt = 0; kt < Dd; kt += BK) {
        const float4 a0 = *reinterpret_cast<const float4*>(A + (size_t)(m0 + lr)      * Dd + kt + lc);
        const float4 a1 = *reinterpret_cast<const float4*>(A + (size_t)(m0 + lr + 64) * Dd + kt + lc);
        const float4 b0 = *reinterpret_cast<const float4*>(B + (size_t)(n0 + lr)      * Dd + kt + lc);
        const float4 b1 = *reinterpret_cast<const float4*>(B + (size_t)(n0 + lr + 64) * Dd + kt + lc);

        As[lc + 0][lr]      = a0.x; As[lc + 1][lr]      = a0.y;
        As[lc + 2][lr]      = a0.z; As[lc + 3][lr]      = a0.w;
        As[lc + 0][lr + 64] = a1.x; As[lc + 1][lr + 64] = a1.y;
        As[lc + 2][lr + 64] = a1.z; As[lc + 3][lr + 64] = a1.w;
        Bs[lc + 0][lr]      = b0.x; Bs[lc + 1][lr]      = b0.y;
        Bs[lc + 2][lr]      = b0.z; Bs[lc + 3][lr]      = b0.w;
        Bs[lc + 0][lr + 64] = b1.x; Bs[lc + 1][lr + 64] = b1.y;
        Bs[lc + 2][lr + 64] = b1.z; Bs[lc + 3][lr + 64] = b1.w;
        __syncthreads();

        #pragma unroll
        for (int k = 0; k < BK; k++) {
            // A pairs load packed for free (rows 2ii,2ii+1 are adjacent floats)
            const ulonglong2 rA0 = *reinterpret_cast<const ulonglong2*>(&As[k][ty * TM]);
            const ulonglong2 rA1 = *reinterpret_cast<const ulonglong2*>(&As[k][ty * TM + 4]);
            const unsigned long long ra2[4] = {rA0.x, rA0.y, rA1.x, rA1.y};

            const float4 rb0 = *reinterpret_cast<const float4*>(&Bs[k][tx * TN]);
            const float4 rb1 = *reinterpret_cast<const float4*>(&Bs[k][tx * TN + 4]);
            const unsigned long long rbd[8] = {
                dupf(rb0.x), dupf(rb0.y), dupf(rb0.z), dupf(rb0.w),
                dupf(rb1.x), dupf(rb1.y), dupf(rb1.z), dupf(rb1.w)};

            #pragma unroll
            for (int ii = 0; ii < TM / 2; ii++)
                #pragma unroll
                for (int j = 0; j < TN; j++)
                    ffma2(acc2[ii][j], ra2[ii], rbd[j]);
        }
        __syncthreads();
    }

    // Epilogue: E = expf(sim / 0.05f)  (unchanged vs the passing kernel)
    #pragma unroll
    for (int ii = 0; ii < TM / 2; ii++) {
        float lo[TN], hi[TN];
        #pragma unroll
        for (int j = 0; j < TN; j++) unpack2(acc2[ii][j], lo[j], hi[j]);

        const int gm0 = m0 + ty * TM + 2 * ii;
        float* d0 = g_E + (size_t)gm0 * Nn + n0 + tx * TN;
        float* d1 = d0 + Nn;

        float4 e0, e1;
        e0.x = expf(lo[0] / 0.05f); e0.y = expf(lo[1] / 0.05f);
        e0.z = expf(lo[2] / 0.05f); e0.w = expf(lo[3] / 0.05f);
        e1.x = expf(lo[4] / 0.05f); e1.y = expf(lo[5] / 0.05f);
        e1.z = expf(lo[6] / 0.05f); e1.w = expf(lo[7] / 0.05f);
        *reinterpret_cast<float4*>(d0)     = e0;
        *reinterpret_cast<float4*>(d0 + 4) = e1;

        e0.x = expf(hi[0] / 0.05f); e0.y = expf(hi[1] / 0.05f);
        e0.z = expf(hi[2] / 0.05f); e0.w = expf(hi[3] / 0.05f);
        e1.x = expf(hi[4] / 0.05f); e1.y = expf(hi[5] / 0.05f);
        e1.z = expf(hi[6] / 0.05f); e1.w = expf(hi[7] / 0.05f);
        *reinterpret_cast<float4*>(d1)     = e0;
        *reinterpret_cast<float4*>(d1 + 4) = e1;
    }
}

// ---------------------------------------------------------------------------
// Row pass: R[m] = 1 / (K * sum_n E[m][n] * (USE_C ? C[n] : 1)).
// Explicit 4x unroll (MLP=4 float4 loads in flight), group-of-4 fp32 pre-sum,
// 4 independent fp64 accumulators (breaks the DADD lat-47 chain).
template <bool USE_C>
__global__ void an_row_reduce_kernel() {
    const int m = blockIdx.x;
    const float4* e  = reinterpret_cast<const float4*>(g_E + (size_t)m * Nn);
    const float4* c4 = reinterpret_cast<const float4*>(g_C);
    double s0 = 0.0, s1 = 0.0, s2 = 0.0, s3 = 0.0;
    // Nn/4 = 8192 float4s; 256 threads -> 32 iters -> 8 unrolled groups of 4
    for (int i = threadIdx.x; i < Nn / 4; i += 1024) {
        float4 v0 = e[i], v1 = e[i + 256], v2 = e[i + 512], v3 = e[i + 768];
        if (USE_C) {
            const float4 c0 = c4[i], c1 = c4[i + 256], c2 = c4[i + 512], c3 = c4[i + 768];
            v0.x *= c0.x; v0.y *= c0.y; v0.z *= c0.z; v0.w *= c0.w;
            v1.x *= c1.x; v1.y *= c1.y; v1.z *= c1.z; v1.w *= c1.w;
            v2.x *= c2.x; v2.y *= c2.y; v2.z *= c2.z; v2.w *= c2.w;
            v3.x *= c3.x; v3.y *= c3.y; v3.z *= c3.z; v3.w *= c3.w;
        }
        s0 += (double)((v0.x + v0.y) + (v0.z + v0.w));
        s1 += (double)((v1.x + v1.y) + (v1.z + v1.w));
        s2 += (double)((v2.x + v2.y) + (v2.z + v2.w));
        s3 += (double)((v3.x + v3.y) + (v3.z + v3.w));
    }
    double s = block_reduce_f64_256((s0 + s1) + (s2 + s3));
    if (threadIdx.x == 0) {
        double r = 1.0 / ((double)Mm * s);
        g_R64[m] = r;
        g_Rf[m]  = (float)r;
    }
}

// Col pass: C[n] = 1 / (B * sum_m E[m][n] * R[m]); one thread per column.
// 16-row unroll (16 independent loads in flight), fp32 tree per group, 2 fp64 accs.
__global__ void an_col_reduce_kernel() {
    __shared__ float sR[Mm];
    for (int i = threadIdx.x; i < Mm; i += 128) sR[i] = g_Rf[i];
    __syncthreads();
    const int n = blockIdx.x * 128 + threadIdx.x;
    const float* base = g_E + n;
    double s0 = 0.0, s1 = 0.0;
    for (int m = 0; m < Mm; m += 16) {
        float t[16];
        #pragma unroll
        for (int j = 0; j < 16; j++)
            t[j] = base[(size_t)(m + j) * Nn] * sR[m + j];
        const float u0 = ((t[0] + t[1]) + (t[2] + t[3])) + ((t[4] + t[5]) + (t[6] + t[7]));
        const float u1 = ((t[8] + t[9]) + (t[10] + t[11])) + ((t[12] + t[13]) + (t[14] + t[15]));
        s0 += (double)u0;
        s1 += (double)u1;
    }
    g_C[n] = (float)(1.0 / ((double)Nn * (s0 + s1)));
}

// Argmax pass: idx[n] = argmax_m E[m][n] * R3[m] (fp32, strict '>' keeps first
// max = jnp.argmax tie-breaking). 8-row unrolled loads; compares stay in m order.
__global__ void an_argmax_kernel() {
    __shared__ float sR[Mm];
    for (int i = threadIdx.x; i < Mm; i += 128) sR[i] = g_Rf[i];
    __syncthreads();
    const int n = blockIdx.x * 128 + threadIdx.x;
    const float* base = g_E + n;
    float best = -1.0f;
    int   bi   = 0;
    for (int m = 0; m < Mm; m += 8) {
        float v[8];
        #pragma unroll
        for (int j = 0; j < 8; j++)
            v[j] = base[(size_t)(m + j) * Nn] * sR[m + j];
        #pragma unroll
        for (int j = 0; j < 8; j++)
            if (v[j] > best) { best = v[j]; bi = m + j; }
    }
    g_idx[n] = bi;
}

// Output: out[n][d] = 0.5 * (proj[n][d] + memory[idx[n]][d])
__global__ void an_output_kernel(const float* __restrict__ proj,
                                 const float* __restrict__ mem,
                                 float* __restrict__ out) {
    const int n  = blockIdx.x;
    const int id = g_idx[n];
    const float4 p = reinterpret_cast<const float4*>(proj + (size_t)n  * Dd)[threadIdx.x];
    const float4 q = reinterpret_cast<const float4*>(mem  + (size_t)id * Dd)[threadIdx.x];
    float4 o;
    o.x = 0.5f * (p.x + q.x);
    o.y = 0.5f * (p.y + q.y);
    o.z = 0.5f * (p.z + q.z);
    o.w = 0.5f * (p.w + q.w);
    reinterpret_cast<float4*>(out + (size_t)n * Dd)[threadIdx.x] = o;
}

// ---------------------------------------------------------------------------
extern "C" void kernel_launch(void* const* d_in, const int* in_sizes, int n_in,
                              void* d_out, int out_size) {
    const float* proj = (const float*)d_in[0];   // [32,1024,1024] -> [N, D]
    const float* mem  = (const float*)d_in[1];   // [1024,1024]    -> [M, D]
    if (n_in >= 2 && in_sizes[0] < in_sizes[1]) {
        const float* t = proj; proj = mem; mem = t;
    }
    float* out = (float*)d_out;

    // 1) l2-normalize rows (fp32 elementwise, like the reference)
    an_normalize_kernel<0><<<Nn, 256>>>(proj);
    an_normalize_kernel<1><<<Mm, 256>>>(mem);

    // 2) E = exp(sim / tau), sim from normalized vectors (ascending-k fp32 FMA)
    dim3 ggrid(Nn / 128, Mm / 128);
    an_gemm_exp_kernel<<<ggrid, 256>>>();

    // 3) Sinkhorn factors, fp64 accumulation (argmax over m only needs R3)
    an_row_reduce_kernel<false><<<Mm, 256>>>();      // R1
    an_col_reduce_kernel<<<Nn / 128, 128>>>();       // C1
    an_row_reduce_kernel<true><<<Mm, 256>>>();       // R2
    an_col_reduce_kernel<<<Nn / 128, 128>>>();       // C2
    an_row_reduce_kernel<true><<<Mm, 256>>>();       // R3

    // 4) per-token argmax over memories, then fused gather + mean
    an_argmax_kernel<<<Nn / 128, 128>>>();
    an_output_kernel<<<Nn, 256>>>(proj, mem, out);
}

// round 9
// speedup vs baseline: 1.3613x; 1.0585x over previous
#include <cuda_runtime.h>
#include <math.h>

// Problem shape (fixed by the dataset: B=32, T=1024, D=1024, M=1024)
namespace {
constexpr int Mm = 1024;             // number of memories (K in sinkhorn)
constexpr int Dd = 1024;             // feature dim
constexpr int Nn = 32768;            // tokens = B*T
}

// Scratch (device globals: allocation-free, per harness rules)
__device__ float  g_E[(size_t)Mm * (size_t)Nn];   // exp(sim/tau), 128 MiB
__device__ float  g_Xn[(size_t)Nn * (size_t)Dd];  // l2-normalized tokens (fp32), 128 MiB
__device__ float  g_Mn[(size_t)Mm * (size_t)Dd];  // l2-normalized memories (fp32), 4 MiB
__device__ double g_R64[Mm];                      // sinkhorn row factors (fp64)
__device__ float  g_Rf[Mm];                       // fp32 copy for argmax scan
__device__ float  g_C[Nn];                        // sinkhorn col factors
__device__ int    g_idx[Nn];                      // argmax memory index per token

// ---------------------------------------------------------------------------
// packed f32x2 helpers (FFMA2: 2 IEEE fp32 FMAs per issue slot; lanes bit-
// identical to scalar FFMA, so per-dot accumulation order is unchanged)
__device__ __forceinline__ void ffma2(unsigned long long& d,
                                      unsigned long long a,
                                      unsigned long long b) {
    asm("fma.rn.f32x2 %0, %1, %2, %0;" : "+l"(d) : "l"(a), "l"(b));
}
__device__ __forceinline__ unsigned long long dupf(float x) {
    unsigned long long r;
    unsigned int u = __float_as_uint(x);
    asm("mov.b64 %0, {%1, %1};" : "=l"(r) : "r"(u));
    return r;
}
__device__ __forceinline__ void unpack2(unsigned long long v, float& lo, float& hi) {
    unsigned int l, h;
    asm("mov.b64 {%0, %1}, %2;" : "=r"(l), "=r"(h) : "l"(v));
    lo = __uint_as_float(l);
    hi = __uint_as_float(h);
}

// ---------------------------------------------------------------------------
// block-wide fp64 sum over 256 threads; result valid in thread 0
__device__ __forceinline__ double block_reduce_f64_256(double s) {
    #pragma unroll
    for (int o = 16; o; o >>= 1) s += __shfl_down_sync(0xffffffffu, s, o);
    __shared__ double red[8];
    if ((threadIdx.x & 31) == 0) red[threadIdx.x >> 5] = s;
    __syncthreads();
    if (threadIdx.x < 32) {
        s = (threadIdx.x < 8) ? red[threadIdx.x] : 0.0;
        #pragma unroll
        for (int o = 4; o; o >>= 1) s += __shfl_down_sync(0xffffffffu, s, o);
    }
    return s;
}

// ---------------------------------------------------------------------------
// Elementwise l2-normalize each row:
//   r = 1.0f / sqrtf(max((float)sumsq, 1e-12f));  out[d] = in[d] * r  (fp32)
template <int TARGET>   // 0 -> g_Xn, 1 -> g_Mn
__global__ void an_normalize_kernel(const float* __restrict__ x) {
    const float4* src = reinterpret_cast<const float4*>(x + (size_t)blockIdx.x * Dd);
    const float4 v = src[threadIdx.x];
    double s = (double)(v.x * v.x + v.y * v.y) + (double)(v.z * v.z + v.w * v.w);
    s = block_reduce_f64_256(s);
    __shared__ float rbc;
    if (threadIdx.x == 0) rbc = 1.0f / sqrtf(fmaxf((float)s, 1e-12f));
    __syncthreads();
    const float r = rbc;
    float4 o;
    o.x = v.x * r; o.y = v.y * r; o.z = v.z * r; o.w = v.w * r;
    float* dst = (TARGET == 0) ? g_Xn : g_Mn;
    reinterpret_cast<float4*>(dst + (size_t)blockIdx.x * Dd)[threadIdx.x] = o;
}

// ---------------------------------------------------------------------------
// GEMM on pre-normalized inputs: sim[m][n] = sum_d Mn[m][d] * Xn[n][d].
// f32x2-packed accumulators (pairwise along m); per-lane single-accumulator
// ascending-d fp32 FMA chain -> bit-identical to scalar version.
// Double-buffered smem: prefetch tile t+1 LDGs before FMA(t), STS after,
// ONE __syncthreads per tile. Epilogue: E = expf(sim / 0.05f).
__global__ __launch_bounds__(256, 2)
void an_gemm_exp_kernel() {
    constexpr int BM = 128, BN = 128, BK = 16, TM = 8, TN = 8;
    constexpr int NTILE = Dd / BK;     // 64
    __shared__ __align__(16) float As[2][BK][BM + 4];
    __shared__ __align__(16) float Bs[2][BK][BN + 4];

    const float* __restrict__ A = g_Mn;
    const float* __restrict__ B = g_Xn;

    const int tid = threadIdx.x;
    const int tx  = tid & 15;
    const int ty  = tid >> 4;
    const int m0  = blockIdx.y * BM;
    const int n0  = blockIdx.x * BN;

    const int lr = tid >> 2;           // 0..63
    const int lc = (tid & 3) << 2;     // 0,4,8,12

    const float* Ab0 = A + (size_t)(m0 + lr)      * Dd + lc;
    const float* Ab1 = A + (size_t)(m0 + lr + 64) * Dd + lc;
    const float* Bb0 = B + (size_t)(n0 + lr)      * Dd + lc;
    const float* Bb1 = B + (size_t)(n0 + lr + 64) * Dd + lc;

    // acc2[ii][j]: lo = row ty*TM+2ii, hi = row ty*TM+2ii+1, col tx*TN+j
    unsigned long long acc2[TM / 2][TN] = {};

    float4 pa0 = *reinterpret_cast<const float4*>(Ab0);
    float4 pa1 = *reinterpret_cast<const float4*>(Ab1);
    float4 pb0 = *reinterpret_cast<const float4*>(Bb0);
    float4 pb1 = *reinterpret_cast<const float4*>(Bb1);

    // store loaded tile into smem buffer `buf`
    auto sts_tile = [&](int buf, const float4& a0, const float4& a1,
                                 const float4& b0, const float4& b1) {
        As[buf][lc + 0][lr]      = a0.x; As[buf][lc + 1][lr]      = a0.y;
        As[buf][lc + 2][lr]      = a0.z; As[buf][lc + 3][lr]      = a0.w;
        As[buf][lc + 0][lr + 64] = a1.x; As[buf][lc + 1][lr + 64] = a1.y;
        As[buf][lc + 2][lr + 64] = a1.z; As[buf][lc + 3][lr + 64] = a1.w;
        Bs[buf][lc + 0][lr]      = b0.x; Bs[buf][lc + 1][lr]      = b0.y;
        Bs[buf][lc + 2][lr]      = b0.z; Bs[buf][lc + 3][lr]      = b0.w;
        Bs[buf][lc + 0][lr + 64] = b1.x; Bs[buf][lc + 1][lr + 64] = b1.y;
        Bs[buf][lc + 2][lr + 64] = b1.z; Bs[buf][lc + 3][lr + 64] = b1.w;
    };

    sts_tile(0, pa0, pa1, pb0, pb1);
    __syncthreads();

    for (int t = 0; t < NTILE; t++) {
        const int cur = t & 1;
        // prefetch next tile's global loads (in flight during the FMA loop)
        if (t + 1 < NTILE) {
            const int off = (t + 1) * BK;
            pa0 = *reinterpret_cast<const float4*>(Ab0 + off);
            pa1 = *reinterpret_cast<const float4*>(Ab1 + off);
            pb0 = *reinterpret_cast<const float4*>(Bb0 + off);
            pb1 = *reinterpret_cast<const float4*>(Bb1 + off);
        }

        #pragma unroll
        for (int k = 0; k < BK; k++) {
            const ulonglong2 rA0 = *reinterpret_cast<const ulonglong2*>(&As[cur][k][ty * TM]);
            const ulonglong2 rA1 = *reinterpret_cast<const ulonglong2*>(&As[cur][k][ty * TM + 4]);
            const unsigned long long ra2[4] = {rA0.x, rA0.y, rA1.x, rA1.y};

            const float4 rb0 = *reinterpret_cast<const float4*>(&Bs[cur][k][tx * TN]);
            const float4 rb1 = *reinterpret_cast<const float4*>(&Bs[cur][k][tx * TN + 4]);
            const unsigned long long rbd[8] = {
                dupf(rb0.x), dupf(rb0.y), dupf(rb0.z), dupf(rb0.w),
                dupf(rb1.x), dupf(rb1.y), dupf(rb1.z), dupf(rb1.w)};

            #pragma unroll
            for (int ii = 0; ii < TM / 2; ii++)
                #pragma unroll
                for (int j = 0; j < TN; j++)
                    ffma2(acc2[ii][j], ra2[ii], rbd[j]);
        }

        if (t + 1 < NTILE) {
            sts_tile(cur ^ 1, pa0, pa1, pb0, pb1);
            __syncthreads();
        }
    }

    // Epilogue: E = expf(sim / 0.05f)  (unchanged; IEEE division + expf)
    #pragma unroll
    for (int ii = 0; ii < TM / 2; ii++) {
        float lo[TN], hi[TN];
        #pragma unroll
        for (int j = 0; j < TN; j++) unpack2(acc2[ii][j], lo[j], hi[j]);

        const int gm0 = m0 + ty * TM + 2 * ii;
        float* d0 = g_E + (size_t)gm0 * Nn + n0 + tx * TN;
        float* d1 = d0 + Nn;

        float4 e0, e1;
        e0.x = expf(lo[0] / 0.05f); e0.y = expf(lo[1] / 0.05f);
        e0.z = expf(lo[2] / 0.05f); e0.w = expf(lo[3] / 0.05f);
        e1.x = expf(lo[4] / 0.05f); e1.y = expf(lo[5] / 0.05f);
        e1.z = expf(lo[6] / 0.05f); e1.w = expf(lo[7] / 0.05f);
        *reinterpret_cast<float4*>(d0)     = e0;
        *reinterpret_cast<float4*>(d0 + 4) = e1;

        e0.x = expf(hi[0] / 0.05f); e0.y = expf(hi[1] / 0.05f);
        e0.z = expf(hi[2] / 0.05f); e0.w = expf(hi[3] / 0.05f);
        e1.x = expf(hi[4] / 0.05f); e1.y = expf(hi[5] / 0.05f);
        e1.z = expf(hi[6] / 0.05f); e1.w = expf(hi[7] / 0.05f);
        *reinterpret_cast<float4*>(d1)     = e0;
        *reinterpret_cast<float4*>(d1 + 4) = e1;
    }
}

// ---------------------------------------------------------------------------
// Row pass: R[m] = 1 / (K * sum_n E[m][n] * (USE_C ? C[n] : 1)).
// 8 float4 loads in flight per thread, group-of-4 fp32 pre-sum, 4 fp64 accs.
template <bool USE_C>
__global__ void an_row_reduce_kernel() {
    const int m = blockIdx.x;
    const float4* e  = reinterpret_cast<const float4*>(g_E + (size_t)m * Nn);
    const float4* c4 = reinterpret_cast<const float4*>(g_C);
    double s0 = 0.0, s1 = 0.0, s2 = 0.0, s3 = 0.0;
    // Nn/4 = 8192 float4s; 256 threads, 8 loads per outer iter -> 4 outer iters
    for (int i = threadIdx.x; i < Nn / 4; i += 2048) {
        float4 v[8];
        #pragma unroll
        for (int j = 0; j < 8; j++) v[j] = e[i + j * 256];
        if (USE_C) {
            float4 c[8];
            #pragma unroll
            for (int j = 0; j < 8; j++) c[j] = c4[i + j * 256];
            #pragma unroll
            for (int j = 0; j < 8; j++) {
                v[j].x *= c[j].x; v[j].y *= c[j].y;
                v[j].z *= c[j].z; v[j].w *= c[j].w;
            }
        }
        s0 += (double)((v[0].x + v[0].y) + (v[0].z + v[0].w));
        s1 += (double)((v[1].x + v[1].y) + (v[1].z + v[1].w));
        s2 += (double)((v[2].x + v[2].y) + (v[2].z + v[2].w));
        s3 += (double)((v[3].x + v[3].y) + (v[3].z + v[3].w));
        s0 += (double)((v[4].x + v[4].y) + (v[4].z + v[4].w));
        s1 += (double)((v[5].x + v[5].y) + (v[5].z + v[5].w));
        s2 += (double)((v[6].x + v[6].y) + (v[6].z + v[6].w));
        s3 += (double)((v[7].x + v[7].y) + (v[7].z + v[7].w));
    }
    double s = block_reduce_f64_256((s0 + s1) + (s2 + s3));
    if (threadIdx.x == 0) {
        double r = 1.0 / ((double)Mm * s);
        g_R64[m] = r;
        g_Rf[m]  = (float)r;
    }
}

// Col pass: C[n] = 1 / (B * sum_m E[m][n] * R[m]); one thread per column.
// 32 independent row loads in flight, fp32 tree per group of 8, 4 fp64 accs.
__global__ void an_col_reduce_kernel() {
    __shared__ float sR[Mm];
    for (int i = threadIdx.x; i < Mm; i += 128) sR[i] = g_Rf[i];
    __syncthreads();
    const int n = blockIdx.x * 128 + threadIdx.x;
    const float* base = g_E + n;
    double s0 = 0.0, s1 = 0.0, s2 = 0.0, s3 = 0.0;
    for (int m = 0; m < Mm; m += 32) {
        float t[32];
        #pragma unroll
        for (int j = 0; j < 32; j++)
            t[j] = base[(size_t)(m + j) * Nn] * sR[m + j];
        const float u0 = ((t[0]  + t[1])  + (t[2]  + t[3]))  + ((t[4]  + t[5])  + (t[6]  + t[7]));
        const float u1 = ((t[8]  + t[9])  + (t[10] + t[11])) + ((t[12] + t[13]) + (t[14] + t[15]));
        const float u2 = ((t[16] + t[17]) + (t[18] + t[19])) + ((t[20] + t[21]) + (t[22] + t[23]));
        const float u3 = ((t[24] + t[25]) + (t[26] + t[27])) + ((t[28] + t[29]) + (t[30] + t[31]));
        s0 += (double)u0; s1 += (double)u1; s2 += (double)u2; s3 += (double)u3;
    }
    g_C[n] = (float)(1.0 / ((double)Nn * ((s0 + s1) + (s2 + s3))));
}

// Argmax pass: idx[n] = argmax_m E[m][n] * R3[m] (fp32, strict '>' keeps first
// max = jnp.argmax tie-breaking). 16 rows in flight; compares in m order.
__global__ void an_argmax_kernel() {
    __shared__ float sR[Mm];
    for (int i = threadIdx.x; i < Mm; i += 128) sR[i] = g_Rf[i];
    __syncthreads();
    const int n = blockIdx.x * 128 + threadIdx.x;
    const float* base = g_E + n;
    float best = -1.0f;
    int   bi   = 0;
    for (int m = 0; m < Mm; m += 16) {
        float v[16];
        #pragma unroll
        for (int j = 0; j < 16; j++)
            v[j] = base[(size_t)(m + j) * Nn] * sR[m + j];
        #pragma unroll
        for (int j = 0; j < 16; j++)
            if (v[j] > best) { best = v[j]; bi = m + j; }
    }
    g_idx[n] = bi;
}

// Output: out[n][d] = 0.5 * (proj[n][d] + memory[idx[n]][d])
__global__ void an_output_kernel(const float* __restrict__ proj,
                                 const float* __restrict__ mem,
                                 float* __restrict__ out) {
    const int n  = blockIdx.x;
    const int id = g_idx[n];
    const float4 p = reinterpret_cast<const float4*>(proj + (size_t)n  * Dd)[threadIdx.x];
    const float4 q = reinterpret_cast<const float4*>(mem  + (size_t)id * Dd)[threadIdx.x];
    float4 o;
    o.x = 0.5f * (p.x + q.x);
    o.y = 0.5f * (p.y + q.y);
    o.z = 0.5f * (p.z + q.z);
    o.w = 0.5f * (p.w + q.w);
    reinterpret_cast<float4*>(out + (size_t)n * Dd)[threadIdx.x] = o;
}

// ---------------------------------------------------------------------------
extern "C" void kernel_launch(void* const* d_in, const int* in_sizes, int n_in,
                              void* d_out, int out_size) {
    const float* proj = (const float*)d_in[0];   // [32,1024,1024] -> [N, D]
    const float* mem  = (const float*)d_in[1];   // [1024,1024]    -> [M, D]
    if (n_in >= 2 && in_sizes[0] < in_sizes[1]) {
        const float* t = proj; proj = mem; mem = t;
    }
    float* out = (float*)d_out;

    // 1) l2-normalize rows (fp32 elementwise, like the reference)
    an_normalize_kernel<0><<<Nn, 256>>>(proj);
    an_normalize_kernel<1><<<Mm, 256>>>(mem);

    // 2) E = exp(sim / tau), sim from normalized vectors (ascending-k fp32 FMA)
    dim3 ggrid(Nn / 128, Mm / 128);
    an_gemm_exp_kernel<<<ggrid, 256>>>();

    // 3) Sinkhorn factors, fp64 accumulation (argmax over m only needs R3)
    an_row_reduce_kernel<false><<<Mm, 256>>>();      // R1
    an_col_reduce_kernel<<<Nn / 128, 128>>>();       // C1
    an_row_reduce_kernel<true><<<Mm, 256>>>();       // R2
    an_col_reduce_kernel<<<Nn / 128, 128>>>();       // C2
    an_row_reduce_kernel<true><<<Mm, 256>>>();       // R3

    // 4) per-token argmax over memories, then fused gather + mean
    an_argmax_kernel<<<Nn / 128, 128>>>();
    an_output_kernel<<<Nn, 256>>>(proj, mem, out);
}